// round 7
// baseline (speedup 1.0000x reference)
#include <cuda_runtime.h>
#include <stdint.h>

// NCA step via tf32 mma.sync.m16n8k8, low-redundancy warp tiling.
// GEMM1: warp = 32d x 32px (B reused for 2 A-tiles). GEMM2: 32d x 16px. GEMM3: 16d x 16px.
// Activations [feature][px] pitch 136 (col-major B operand); weights in registers from gmem/L2.

#define HW   256
#define CH   16
#define TW   16
#define TH   8
#define NPIX 128
#define YP   136
#define XCS  184
#define DP   20

#define OFF_YS   0
#define OFF_H1S  6528
#define OFF_H2S  15232
#define OFF_DXT  19584
#define OFF_XS   22144
#define OFF_B1   25088
#define OFF_B2   25152
#define OFF_B3   25184
#define OFF_MS   25200
#define SMEM_FLOATS 25328
#define SMEM_BYTES  (SMEM_FLOATS * 4)

static_assert(OFF_H1S == OFF_YS  + 48 * YP, "ys");
static_assert(OFF_H2S == OFF_H1S + 64 * YP, "h1s");
static_assert(OFF_DXT == OFF_H2S + 32 * YP, "h2s");
static_assert(OFF_XS  == OFF_DXT + 128 * DP, "dxT");
static_assert(OFF_B1  == OFF_XS  + 16 * XCS, "xs");
static_assert(OFF_MS + NPIX == SMEM_FLOATS, "total");
static_assert(2 * SMEM_BYTES <= 227 * 1024, "2 CTA/SM");

__device__ __forceinline__ float tanh_fast(float v) {
    float y;
    asm("tanh.approx.f32 %0, %1;" : "=f"(y) : "f"(v));
    return y;
}
__device__ __forceinline__ uint32_t f2tf(float f) {
    uint32_t u;
    asm("cvt.rna.tf32.f32 %0, %1;" : "=r"(u) : "f"(f));
    return u;
}
__device__ __forceinline__ float f2tff(float f) { return __uint_as_float(f2tf(f)); }

__device__ __forceinline__ void mma_tf32(float& c0, float& c1, float& c2, float& c3,
                                         uint32_t a0, uint32_t a1, uint32_t a2, uint32_t a3,
                                         uint32_t b0, uint32_t b1)
{
    asm volatile(
        "mma.sync.aligned.m16n8k8.row.col.f32.tf32.tf32.f32 "
        "{%0,%1,%2,%3},{%4,%5,%6,%7},{%8,%9},{%0,%1,%2,%3};"
        : "+f"(c0), "+f"(c1), "+f"(c2), "+f"(c3)
        : "r"(a0), "r"(a1), "r"(a2), "r"(a3), "r"(b0), "r"(b1));
}

__global__ __launch_bounds__(256, 2)
void nca_step_kernel(const float* __restrict__ x,
                     const float* __restrict__ w1, const float* __restrict__ b1,
                     const float* __restrict__ w2, const float* __restrict__ b2,
                     const float* __restrict__ w3, const float* __restrict__ b3,
                     const uint32_t* __restrict__ mask,
                     float* __restrict__ out)
{
    extern __shared__ float sm[];
    float* ys  = sm + OFF_YS;
    float* h1s = sm + OFF_H1S;
    float* h2s = sm + OFF_H2S;
    float* dxT = sm + OFF_DXT;
    float* xs  = sm + OFF_XS;
    float* b1s = sm + OFF_B1;
    float* b2s = sm + OFF_B2;
    float* b3s = sm + OFF_B3;
    float* ms  = sm + OFF_MS;

    const int tid = threadIdx.x;
    const int bx = blockIdx.x, by = blockIdx.y, bb = blockIdx.z;
    const int y0 = by * TH, x0 = bx * TW;

    // ---------------- phase 0: biases / mask / halo ----------------
    if (tid < 64)       b1s[tid] = b1[tid];
    else if (tid < 96)  b2s[tid - 64] = b2[tid - 64];
    else if (tid < 112) b3s[tid - 96] = b3[tid - 96];

    if (tid < NPIX) {
        int py = tid >> 4, xx = tid & 15;
        uint32_t w = mask[((size_t)bb * HW + (y0 + py)) * HW + (x0 + xx)];
        ms[tid] = (w != 0u) ? 1.f : 0.f;
    }

    {   // halo 10x18, channel-major, zero-pad outside image
        const float* xb = x + (size_t)bb * HW * HW * CH;
        const int gy0 = y0 - 1, gx0 = x0 - 1;
        for (int i = tid; i < 10 * 18 * 4; i += 256) {
            int q = i & 3, pix = i >> 2;
            int r = pix / 18, cc = pix - r * 18;
            int gr = gy0 + r, gc = gx0 + cc;
            float4 v = make_float4(0.f, 0.f, 0.f, 0.f);
            if ((unsigned)gr < HW && (unsigned)gc < HW)
                v = *(const float4*)&xb[((size_t)gr * HW + gc) * CH + q * 4];
            int base = r * 18 + cc;
            xs[(4 * q + 0) * XCS + base] = v.x;
            xs[(4 * q + 1) * XCS + base] = v.y;
            xs[(4 * q + 2) * XCS + base] = v.z;
            xs[(4 * q + 3) * XCS + base] = v.w;
        }
    }
    __syncthreads();

    // ---------------- phase 1: stencil -> ys[48][128] (tf32-rounded) ----------------
    {
        const int c = tid >> 4, xx = tid & 15;
        const float* xc = xs + c * XCS;
        float r0a = xc[xx],      r0b = xc[xx + 1],      r0c = xc[xx + 2];
        float r1a = xc[18 + xx], r1b = xc[18 + xx + 1], r1c = xc[18 + xx + 2];
        float* yI = ys + (3 * c + 0) * YP;
        float* yX = ys + (3 * c + 1) * YP;
        float* yY = ys + (3 * c + 2) * YP;
        #pragma unroll
        for (int py = 0; py < TH; py++) {
            const float* row2 = xc + (py + 2) * 18 + xx;
            float r2a = row2[0], r2b = row2[1], r2c = row2[2];
            float gx = ((r0c - r0a) + 2.f * (r1c - r1a) + (r2c - r2a)) * 0.125f;
            float gy = ((r2a - r0a) + 2.f * (r2b - r0b) + (r2c - r0c)) * 0.125f;
            int p = py * 16 + xx;
            yI[p] = f2tff(r1b);
            yX[p] = f2tff(gx);
            yY[p] = f2tff(gy);
            r0a = r1a; r0b = r1b; r0c = r1c;
            r1a = r2a; r1b = r2b; r1c = r2c;
        }
    }
    __syncthreads();

    const int lane = tid & 31, warp = tid >> 5;
    const int g = lane >> 2, t = lane & 3;

    // ---------------- phase 2: GEMM1 h1[64][128] = tanh(W1^T @ ys + b1) ----------------
    // warp tile: 32d x 32px; slab s = warp&3 (px), d-half dh = warp>>2.
    {
        const int s = warp & 3, dh = warp >> 2;
        const int d0 = dh * 32;
        uint32_t A[6][2][4];
        #pragma unroll
        for (int kt = 0; kt < 6; kt++) {
            int k0 = kt * 8;
            #pragma unroll
            for (int mt = 0; mt < 2; mt++) {
                int dm = d0 + mt * 16;
                A[kt][mt][0] = f2tf(w1[(k0 + t) * 64 + dm + g]);
                A[kt][mt][1] = f2tf(w1[(k0 + t) * 64 + dm + g + 8]);
                A[kt][mt][2] = f2tf(w1[(k0 + t + 4) * 64 + dm + g]);
                A[kt][mt][3] = f2tf(w1[(k0 + t + 4) * 64 + dm + g + 8]);
            }
        }
        float acc[2][4][4];
        #pragma unroll
        for (int mt = 0; mt < 2; mt++) {
            float bl = b1s[d0 + mt * 16 + g], bh = b1s[d0 + mt * 16 + g + 8];
            #pragma unroll
            for (int nt = 0; nt < 4; nt++) {
                acc[mt][nt][0] = bl; acc[mt][nt][1] = bl;
                acc[mt][nt][2] = bh; acc[mt][nt][3] = bh;
            }
        }
        #pragma unroll
        for (int kt = 0; kt < 6; kt++) {
            int k0 = kt * 8;
            #pragma unroll
            for (int nt = 0; nt < 4; nt++) {
                int px0 = s * 32 + nt * 8;
                uint32_t bv0 = __float_as_uint(ys[(k0 + t) * YP + px0 + g]);
                uint32_t bv1 = __float_as_uint(ys[(k0 + t + 4) * YP + px0 + g]);
                #pragma unroll
                for (int mt = 0; mt < 2; mt++)
                    mma_tf32(acc[mt][nt][0], acc[mt][nt][1], acc[mt][nt][2], acc[mt][nt][3],
                             A[kt][mt][0], A[kt][mt][1], A[kt][mt][2], A[kt][mt][3], bv0, bv1);
            }
        }
        #pragma unroll
        for (int mt = 0; mt < 2; mt++) {
            int dm = d0 + mt * 16;
            #pragma unroll
            for (int nt = 0; nt < 4; nt++) {
                int px0 = s * 32 + nt * 8;
                float2 lo = make_float2(f2tff(tanh_fast(acc[mt][nt][0])), f2tff(tanh_fast(acc[mt][nt][1])));
                float2 hi = make_float2(f2tff(tanh_fast(acc[mt][nt][2])), f2tff(tanh_fast(acc[mt][nt][3])));
                *(float2*)&h1s[(dm + g) * YP + px0 + 2 * t]     = lo;
                *(float2*)&h1s[(dm + g + 8) * YP + px0 + 2 * t] = hi;
            }
        }
    }
    __syncthreads();

    // ---------------- phase 3: GEMM2 h2[32][128] = tanh(W2^T @ h1 + b2) ----------------
    // warp tile: 32d x 16px; slab s = warp (8 slabs of 16 px). Zero B redundancy.
    {
        const int s = warp;
        uint32_t A[8][2][4];
        #pragma unroll
        for (int kt = 0; kt < 8; kt++) {
            int k0 = kt * 8;
            #pragma unroll
            for (int mt = 0; mt < 2; mt++) {
                int dm = mt * 16;
                A[kt][mt][0] = f2tf(w2[(k0 + t) * 32 + dm + g]);
                A[kt][mt][1] = f2tf(w2[(k0 + t) * 32 + dm + g + 8]);
                A[kt][mt][2] = f2tf(w2[(k0 + t + 4) * 32 + dm + g]);
                A[kt][mt][3] = f2tf(w2[(k0 + t + 4) * 32 + dm + g + 8]);
            }
        }
        float acc[2][2][4];
        #pragma unroll
        for (int mt = 0; mt < 2; mt++) {
            float bl = b2s[mt * 16 + g], bh = b2s[mt * 16 + g + 8];
            #pragma unroll
            for (int nt = 0; nt < 2; nt++) {
                acc[mt][nt][0] = bl; acc[mt][nt][1] = bl;
                acc[mt][nt][2] = bh; acc[mt][nt][3] = bh;
            }
        }
        #pragma unroll
        for (int kt = 0; kt < 8; kt++) {
            int k0 = kt * 8;
            #pragma unroll
            for (int nt = 0; nt < 2; nt++) {
                int px0 = s * 16 + nt * 8;
                uint32_t bv0 = __float_as_uint(h1s[(k0 + t) * YP + px0 + g]);
                uint32_t bv1 = __float_as_uint(h1s[(k0 + t + 4) * YP + px0 + g]);
                #pragma unroll
                for (int mt = 0; mt < 2; mt++)
                    mma_tf32(acc[mt][nt][0], acc[mt][nt][1], acc[mt][nt][2], acc[mt][nt][3],
                             A[kt][mt][0], A[kt][mt][1], A[kt][mt][2], A[kt][mt][3], bv0, bv1);
            }
        }
        #pragma unroll
        for (int mt = 0; mt < 2; mt++) {
            int dm = mt * 16;
            #pragma unroll
            for (int nt = 0; nt < 2; nt++) {
                int px0 = s * 16 + nt * 8;
                float2 lo = make_float2(f2tff(tanh_fast(acc[mt][nt][0])), f2tff(tanh_fast(acc[mt][nt][1])));
                float2 hi = make_float2(f2tff(tanh_fast(acc[mt][nt][2])), f2tff(tanh_fast(acc[mt][nt][3])));
                *(float2*)&h2s[(dm + g) * YP + px0 + 2 * t]     = lo;
                *(float2*)&h2s[(dm + g + 8) * YP + px0 + 2 * t] = hi;
            }
        }
    }
    __syncthreads();

    // ---------------- phase 4: GEMM3 dx[16][128] = W3^T @ h2 + b3 -> dxT[px][d] ----------------
    {
        const int s = warp;
        uint32_t A[4][4];
        #pragma unroll
        for (int kt = 0; kt < 4; kt++) {
            int k0 = kt * 8;
            A[kt][0] = f2tf(w3[(k0 + t) * 16 + g]);
            A[kt][1] = f2tf(w3[(k0 + t) * 16 + g + 8]);
            A[kt][2] = f2tf(w3[(k0 + t + 4) * 16 + g]);
            A[kt][3] = f2tf(w3[(k0 + t + 4) * 16 + g + 8]);
        }
        const float bl = b3s[g], bh = b3s[g + 8];
        #pragma unroll
        for (int nt = 0; nt < 2; nt++) {
            const int px0 = s * 16 + nt * 8;
            float c0 = bl, c1 = bl, c2 = bh, c3 = bh;
            #pragma unroll
            for (int kt = 0; kt < 4; kt++) {
                int k0 = kt * 8;
                uint32_t bv0 = __float_as_uint(h2s[(k0 + t) * YP + px0 + g]);
                uint32_t bv1 = __float_as_uint(h2s[(k0 + t + 4) * YP + px0 + g]);
                mma_tf32(c0, c1, c2, c3, A[kt][0], A[kt][1], A[kt][2], A[kt][3], bv0, bv1);
            }
            dxT[(px0 + 2 * t) * DP + g]         = c0;
            dxT[(px0 + 2 * t + 1) * DP + g]     = c1;
            dxT[(px0 + 2 * t) * DP + g + 8]     = c2;
            dxT[(px0 + 2 * t + 1) * DP + g + 8] = c3;
        }
    }
    __syncthreads();

    // ---------------- phase 5: out = x + dx*mask ----------------
    {
        const int px = tid >> 1;
        const int c0 = (tid & 1) * 8;
        const int py = px >> 4, xx = px & 15;
        const float m = ms[px];
        const float* d = dxT + px * DP + c0;
        const int hbase = (py + 1) * 18 + (xx + 1);
        float* o = out + (((size_t)bb * HW + (y0 + py)) * HW + (x0 + xx)) * CH + c0;
        float4 r0, r1;
        r0.x = xs[(c0 + 0) * XCS + hbase] + d[0] * m;
        r0.y = xs[(c0 + 1) * XCS + hbase] + d[1] * m;
        r0.z = xs[(c0 + 2) * XCS + hbase] + d[2] * m;
        r0.w = xs[(c0 + 3) * XCS + hbase] + d[3] * m;
        r1.x = xs[(c0 + 4) * XCS + hbase] + d[4] * m;
        r1.y = xs[(c0 + 5) * XCS + hbase] + d[5] * m;
        r1.z = xs[(c0 + 6) * XCS + hbase] + d[6] * m;
        r1.w = xs[(c0 + 7) * XCS + hbase] + d[7] * m;
        *(float4*)&o[0] = r0;
        *(float4*)&o[4] = r1;
    }
}

extern "C" void kernel_launch(void* const* d_in, const int* in_sizes, int n_in,
                              void* d_out, int out_size)
{
    const float* x  = (const float*)d_in[0];
    const float* w1 = (const float*)d_in[1];
    const float* b1 = (const float*)d_in[2];
    const float* w2 = (const float*)d_in[3];
    const float* b2 = (const float*)d_in[4];
    const float* w3 = (const float*)d_in[5];
    const float* b3 = (const float*)d_in[6];
    const uint32_t* mask = (const uint32_t*)d_in[7];
    float* out = (float*)d_out;

    cudaFuncSetAttribute(nca_step_kernel,
                         cudaFuncAttributeMaxDynamicSharedMemorySize, SMEM_BYTES);
    dim3 grid(HW / TW, HW / TH, 16);
    nca_step_kernel<<<grid, 256, SMEM_BYTES>>>(x, w1, b1, w2, b2, w3, b3, mask, out);
}

// round 8
// speedup vs baseline: 1.2767x; 1.2767x over previous
#include <cuda_runtime.h>
#include <stdint.h>

// NCA step via tf32 mma.sync.m16n8k8 (R6 tiling), smem-aliased, fused GEMM3 epilogue.
// 3 CTAs/SM (71.9 KB smem/CTA). h2s aliases ys (dead after GEMM1); no dxT buffer.

#define HW   256
#define CH   16
#define TW   16
#define TH   8
#define NPIX 128
#define YP   136      // pitch: B-fragment LDS conflict-free
#define XCS  184      // halo channel stride xs[16][10*18]

#define OFF_YS   0            // 48*136 = 6528 ; h2s (32*136=4352) aliases this
#define OFF_H1S  6528         // 64*136 = 8704
#define OFF_XS   15232        // 16*184 = 2944
#define OFF_B1   18176
#define OFF_B2   18240
#define OFF_B3   18272
#define OFF_MS   18288
#define SMEM_FLOATS 18416
#define SMEM_BYTES  (SMEM_FLOATS * 4)

static_assert(OFF_H1S == OFF_YS + 48 * YP, "ys");
static_assert(OFF_XS  == OFF_H1S + 64 * YP, "h1s");
static_assert(OFF_B1  == OFF_XS + 16 * XCS, "xs");
static_assert(OFF_MS + NPIX == SMEM_FLOATS, "total");
static_assert(3 * SMEM_BYTES <= 227 * 1024, "3 CTA/SM");

__device__ __forceinline__ float tanh_fast(float v) {
    float y;
    asm("tanh.approx.f32 %0, %1;" : "=f"(y) : "f"(v));
    return y;
}
__device__ __forceinline__ uint32_t f2tf(float f) {
    uint32_t u;
    asm("cvt.rna.tf32.f32 %0, %1;" : "=r"(u) : "f"(f));
    return u;
}
__device__ __forceinline__ float f2tff(float f) { return __uint_as_float(f2tf(f)); }

__device__ __forceinline__ void mma_tf32(float& c0, float& c1, float& c2, float& c3,
                                         uint32_t a0, uint32_t a1, uint32_t a2, uint32_t a3,
                                         uint32_t b0, uint32_t b1)
{
    asm volatile(
        "mma.sync.aligned.m16n8k8.row.col.f32.tf32.tf32.f32 "
        "{%0,%1,%2,%3},{%4,%5,%6,%7},{%8,%9},{%0,%1,%2,%3};"
        : "+f"(c0), "+f"(c1), "+f"(c2), "+f"(c3)
        : "r"(a0), "r"(a1), "r"(a2), "r"(a3), "r"(b0), "r"(b1));
}

__global__ __launch_bounds__(256, 3)
void nca_step_kernel(const float* __restrict__ x,
                     const float* __restrict__ w1, const float* __restrict__ b1,
                     const float* __restrict__ w2, const float* __restrict__ b2,
                     const float* __restrict__ w3, const float* __restrict__ b3,
                     const uint32_t* __restrict__ mask,
                     float* __restrict__ out)
{
    extern __shared__ float sm[];
    float* ys  = sm + OFF_YS;
    float* h2s = sm + OFF_YS;     // alias: ys dead after GEMM1 barrier
    float* h1s = sm + OFF_H1S;
    float* xs  = sm + OFF_XS;
    float* b1s = sm + OFF_B1;
    float* b2s = sm + OFF_B2;
    float* b3s = sm + OFF_B3;
    float* ms  = sm + OFF_MS;

    const int tid = threadIdx.x;
    const int bx = blockIdx.x, by = blockIdx.y, bb = blockIdx.z;
    const int y0 = by * TH, x0 = bx * TW;

    // ---------------- phase 0: biases / mask / halo ----------------
    if (tid < 64)       b1s[tid] = b1[tid];
    else if (tid < 96)  b2s[tid - 64] = b2[tid - 64];
    else if (tid < 112) b3s[tid - 96] = b3[tid - 96];

    if (tid < NPIX) {
        int py = tid >> 4, xx = tid & 15;
        uint32_t w = mask[((size_t)bb * HW + (y0 + py)) * HW + (x0 + xx)];
        ms[tid] = (w != 0u) ? 1.f : 0.f;
    }

    {   // halo 10x18, channel-major, zero-pad outside image
        const float* xb = x + (size_t)bb * HW * HW * CH;
        const int gy0 = y0 - 1, gx0 = x0 - 1;
        for (int i = tid; i < 10 * 18 * 4; i += 256) {
            int q = i & 3, pix = i >> 2;
            int r = pix / 18, cc = pix - r * 18;
            int gr = gy0 + r, gc = gx0 + cc;
            float4 v = make_float4(0.f, 0.f, 0.f, 0.f);
            if ((unsigned)gr < HW && (unsigned)gc < HW)
                v = *(const float4*)&xb[((size_t)gr * HW + gc) * CH + q * 4];
            int base = r * 18 + cc;
            xs[(4 * q + 0) * XCS + base] = v.x;
            xs[(4 * q + 1) * XCS + base] = v.y;
            xs[(4 * q + 2) * XCS + base] = v.z;
            xs[(4 * q + 3) * XCS + base] = v.w;
        }
    }
    __syncthreads();

    // ---------------- phase 1: stencil -> ys[48][128] (tf32-rounded) ----------------
    {
        const int c = tid >> 4, xx = tid & 15;
        const float* xc = xs + c * XCS;
        float r0a = xc[xx],      r0b = xc[xx + 1],      r0c = xc[xx + 2];
        float r1a = xc[18 + xx], r1b = xc[18 + xx + 1], r1c = xc[18 + xx + 2];
        float* yI = ys + (3 * c + 0) * YP;
        float* yX = ys + (3 * c + 1) * YP;
        float* yY = ys + (3 * c + 2) * YP;
        #pragma unroll
        for (int py = 0; py < TH; py++) {
            const float* row2 = xc + (py + 2) * 18 + xx;
            float r2a = row2[0], r2b = row2[1], r2c = row2[2];
            float gx = ((r0c - r0a) + 2.f * (r1c - r1a) + (r2c - r2a)) * 0.125f;
            float gy = ((r2a - r0a) + 2.f * (r2b - r0b) + (r2c - r0c)) * 0.125f;
            int p = py * 16 + xx;
            yI[p] = f2tff(r1b);
            yX[p] = f2tff(gx);
            yY[p] = f2tff(gy);
            r0a = r1a; r0b = r1b; r0c = r1c;
            r1a = r2a; r1b = r2b; r1c = r2c;
        }
    }
    __syncthreads();

    const int lane = tid & 31, warp = tid >> 5;
    const int g = lane >> 2, t = lane & 3;

    // ---------------- phase 2: GEMM1 h1[64][128] = tanh(W1^T @ ys + b1) ----------------
    {
        const int d0 = (warp & 3) * 16;
        const int pb = (warp >> 2) * 64;
        uint32_t A[6][4];
        #pragma unroll
        for (int kt = 0; kt < 6; kt++) {
            int k0 = kt * 8;
            A[kt][0] = f2tf(w1[(k0 + t) * 64 + d0 + g]);
            A[kt][1] = f2tf(w1[(k0 + t) * 64 + d0 + g + 8]);
            A[kt][2] = f2tf(w1[(k0 + t + 4) * 64 + d0 + g]);
            A[kt][3] = f2tf(w1[(k0 + t + 4) * 64 + d0 + g + 8]);
        }
        const float bl = b1s[d0 + g], bh = b1s[d0 + g + 8];
        #pragma unroll
        for (int nt = 0; nt < 8; nt++) {
            const int px0 = pb + nt * 8;
            float c0 = bl, c1 = bl, c2 = bh, c3 = bh;
            #pragma unroll
            for (int kt = 0; kt < 6; kt++) {
                int k0 = kt * 8;
                uint32_t bv0 = __float_as_uint(ys[(k0 + t) * YP + px0 + g]);
                uint32_t bv1 = __float_as_uint(ys[(k0 + t + 4) * YP + px0 + g]);
                mma_tf32(c0, c1, c2, c3, A[kt][0], A[kt][1], A[kt][2], A[kt][3], bv0, bv1);
            }
            float2 lo = make_float2(f2tff(tanh_fast(c0)), f2tff(tanh_fast(c1)));
            float2 hi = make_float2(f2tff(tanh_fast(c2)), f2tff(tanh_fast(c3)));
            *(float2*)&h1s[(d0 + g) * YP + px0 + 2 * t]     = lo;
            *(float2*)&h1s[(d0 + g + 8) * YP + px0 + 2 * t] = hi;
        }
    }
    __syncthreads();   // ys reads done -> h2s may overwrite the aliased region

    // ---------------- phase 3: GEMM2 h2[32][128] = tanh(W2^T @ h1 + b2) ----------------
    {
        const int d0 = (warp & 1) * 16;
        const int pb = (warp >> 1) * 32;
        uint32_t A[8][4];
        #pragma unroll
        for (int kt = 0; kt < 8; kt++) {
            int k0 = kt * 8;
            A[kt][0] = f2tf(w2[(k0 + t) * 32 + d0 + g]);
            A[kt][1] = f2tf(w2[(k0 + t) * 32 + d0 + g + 8]);
            A[kt][2] = f2tf(w2[(k0 + t + 4) * 32 + d0 + g]);
            A[kt][3] = f2tf(w2[(k0 + t + 4) * 32 + d0 + g + 8]);
        }
        const float bl = b2s[d0 + g], bh = b2s[d0 + g + 8];
        #pragma unroll
        for (int nt = 0; nt < 4; nt++) {
            const int px0 = pb + nt * 8;
            float c0 = bl, c1 = bl, c2 = bh, c3 = bh;
            #pragma unroll
            for (int kt = 0; kt < 8; kt++) {
                int k0 = kt * 8;
                uint32_t bv0 = __float_as_uint(h1s[(k0 + t) * YP + px0 + g]);
                uint32_t bv1 = __float_as_uint(h1s[(k0 + t + 4) * YP + px0 + g]);
                mma_tf32(c0, c1, c2, c3, A[kt][0], A[kt][1], A[kt][2], A[kt][3], bv0, bv1);
            }
            float2 lo = make_float2(f2tff(tanh_fast(c0)), f2tff(tanh_fast(c1)));
            float2 hi = make_float2(f2tff(tanh_fast(c2)), f2tff(tanh_fast(c3)));
            *(float2*)&h2s[(d0 + g) * YP + px0 + 2 * t]     = lo;
            *(float2*)&h2s[(d0 + g + 8) * YP + px0 + 2 * t] = hi;
        }
    }
    __syncthreads();

    // ---------------- phase 4: GEMM3 dx = W3^T @ h2 + b3, fused epilogue ----------------
    {
        uint32_t A[4][4];
        #pragma unroll
        for (int kt = 0; kt < 4; kt++) {
            int k0 = kt * 8;
            A[kt][0] = f2tf(w3[(k0 + t) * 16 + g]);
            A[kt][1] = f2tf(w3[(k0 + t) * 16 + g + 8]);
            A[kt][2] = f2tf(w3[(k0 + t + 4) * 16 + g]);
            A[kt][3] = f2tf(w3[(k0 + t + 4) * 16 + g + 8]);
        }
        const float bl = b3s[g], bh = b3s[g + 8];
        float* ob = out + (((size_t)bb * HW + y0) * HW + x0) * CH;
        #pragma unroll
        for (int nt = 0; nt < 2; nt++) {
            const int px0 = warp * 16 + nt * 8;
            float c0 = bl, c1 = bl, c2 = bh, c3 = bh;
            #pragma unroll
            for (int kt = 0; kt < 4; kt++) {
                int k0 = kt * 8;
                uint32_t bv0 = __float_as_uint(h2s[(k0 + t) * YP + px0 + g]);
                uint32_t bv1 = __float_as_uint(h2s[(k0 + t + 4) * YP + px0 + g]);
                mma_tf32(c0, c1, c2, c3, A[kt][0], A[kt][1], A[kt][2], A[kt][3], bv0, bv1);
            }
            // fragment -> out: pixels p0=px0+2t, p1=p0+1; channels g, g+8
            const int p0 = px0 + 2 * t, p1 = p0 + 1;
            const float m0 = ms[p0], m1 = ms[p1];
            const int py0 = p0 >> 4, xx0 = p0 & 15;
            const int py1 = p1 >> 4, xx1 = p1 & 15;
            const int hb0 = (py0 + 1) * 18 + (xx0 + 1);
            const int hb1 = (py1 + 1) * 18 + (xx1 + 1);
            // out offset within tile: pixel p -> (py*HW + xx)*CH + ch
            float* o0 = ob + ((size_t)py0 * HW + xx0) * CH;
            float* o1 = ob + ((size_t)py1 * HW + xx1) * CH;
            o0[g]     = xs[g * XCS + hb0]       + c0 * m0;
            o1[g]     = xs[g * XCS + hb1]       + c1 * m1;
            o0[g + 8] = xs[(g + 8) * XCS + hb0] + c2 * m0;
            o1[g + 8] = xs[(g + 8) * XCS + hb1] + c3 * m1;
        }
    }
}

extern "C" void kernel_launch(void* const* d_in, const int* in_sizes, int n_in,
                              void* d_out, int out_size)
{
    const float* x  = (const float*)d_in[0];
    const float* w1 = (const float*)d_in[1];
    const float* b1 = (const float*)d_in[2];
    const float* w2 = (const float*)d_in[3];
    const float* b2 = (const float*)d_in[4];
    const float* w3 = (const float*)d_in[5];
    const float* b3 = (const float*)d_in[6];
    const uint32_t* mask = (const uint32_t*)d_in[7];
    float* out = (float*)d_out;

    cudaFuncSetAttribute(nca_step_kernel,
                         cudaFuncAttributeMaxDynamicSharedMemorySize, SMEM_BYTES);
    dim3 grid(HW / TW, HW / TH, 16);
    nca_step_kernel<<<grid, 256, SMEM_BYTES>>>(x, w1, b1, w2, b2, w3, b3, mask, out);
}

// round 9
// speedup vs baseline: 1.7071x; 1.3372x over previous
#include <cuda_runtime.h>
#include <cuda_fp16.h>
#include <stdint.h>

// NCA step via fp16 mma.sync.m16n8k16.
// Activations stored [k-pair][px] as half2-packed u32 (pitch 136 u32, conflict-free).
// Weight fragments pre-staged in smem in fragment order -> A loads are LDS.128.
// 4 CTAs/SM target (53.2 KB smem). Fused GEMM3 epilogue.

#define HW   256
#define CH   16
#define TW   16
#define TH   8
#define NPIX 128
#define YPP  136      // u32 pitch for packed activation rows
#define XCS  184      // fp32 halo channel stride xs[16][10*18]

// u32-unit offsets
#define OFF_YS   0          // 24 pair-rows * 136 = 3264 ; h2 (16*136=2176) aliases
#define OFF_H1   3264       // 32 * 136 = 4352
#define OFF_XS   7616       // fp32 halo: 16*184 = 2944
#define OFF_WF1  10560      // 4*3*32*4 = 1536
#define OFF_WF2  12096      // 2*4*32*4 = 1024
#define OFF_WF3  13120      // 1*2*32*4 = 256
#define OFF_B1   13376
#define OFF_B2   13440
#define OFF_B3   13472
#define OFF_MS   13488
#define SMEM_U32 13616
#define SMEM_BYTES (SMEM_U32 * 4)

static_assert(OFF_H1  == OFF_YS + 24 * YPP, "ys");
static_assert(OFF_XS  == OFF_H1 + 32 * YPP, "h1");
static_assert(OFF_WF1 == OFF_XS + 16 * XCS, "xs");
static_assert(OFF_WF2 == OFF_WF1 + 1536, "wf1");
static_assert(OFF_WF3 == OFF_WF2 + 1024, "wf2");
static_assert(OFF_B1  == OFF_WF3 + 256, "wf3");
static_assert(OFF_MS + NPIX == SMEM_U32, "total");
static_assert(4 * SMEM_BYTES <= 227 * 1024, "4 CTA/SM");

__device__ __forceinline__ float tanh_fast(float v) {
    float y;
    asm("tanh.approx.f32 %0, %1;" : "=f"(y) : "f"(v));
    return y;
}
__device__ __forceinline__ uint32_t pack2h(float a, float b) {
    __half2 h = __floats2half2_rn(a, b);       // a -> low
    return *(uint32_t*)&h;
}
__device__ __forceinline__ uint32_t lows2(uint32_t x, uint32_t y)  { return __byte_perm(x, y, 0x5410); }
__device__ __forceinline__ uint32_t highs2(uint32_t x, uint32_t y) { return __byte_perm(x, y, 0x7632); }

__device__ __forceinline__ void mma_f16(float& c0, float& c1, float& c2, float& c3,
                                        uint32_t a0, uint32_t a1, uint32_t a2, uint32_t a3,
                                        uint32_t b0, uint32_t b1)
{
    asm volatile(
        "mma.sync.aligned.m16n8k16.row.col.f32.f16.f16.f32 "
        "{%0,%1,%2,%3},{%4,%5,%6,%7},{%8,%9},{%0,%1,%2,%3};"
        : "+f"(c0), "+f"(c1), "+f"(c2), "+f"(c3)
        : "r"(a0), "r"(a1), "r"(a2), "r"(a3), "r"(b0), "r"(b1));
}

// Stage weights [K= KT*16][D] (fp32, d-contiguous) into fragment order:
// dst[((dt*KT + kt)*32 + lane)*4 + reg] = half2{ w[2kp][d], w[2kp+1][d] }
template<int D, int KT>
__device__ __forceinline__ void stage_w(const float* __restrict__ w, uint32_t* dst, int tid)
{
    #pragma unroll 1
    for (int p = tid; p < 8 * KT * D; p += 256) {
        int kp = p / D, d = p % D;                 // consecutive tid -> consecutive d (coalesced)
        int kt = kp >> 3, kl = kp & 7;
        int t = kl & 3, khalf = kl >> 2;
        int dt = d >> 4, g = d & 7, rhi = (d >> 3) & 1;
        int reg = khalf * 2 + rhi, lane = g * 4 + t;
        float lo = w[(2 * kp) * D + d];
        float hi = w[(2 * kp + 1) * D + d];
        dst[((dt * KT + kt) * 32 + lane) * 4 + reg] = pack2h(lo, hi);
    }
}

__global__ __launch_bounds__(256, 4)
void nca_step_kernel(const float* __restrict__ x,
                     const float* __restrict__ w1, const float* __restrict__ b1,
                     const float* __restrict__ w2, const float* __restrict__ b2,
                     const float* __restrict__ w3, const float* __restrict__ b3,
                     const uint32_t* __restrict__ mask,
                     float* __restrict__ out)
{
    extern __shared__ uint32_t smu[];
    uint32_t* ysU = smu + OFF_YS;     // 24 pair-rows
    uint32_t* h2U = smu + OFF_YS;     // alias: ys dead after GEMM1 barrier (16 pair-rows)
    uint32_t* h1U = smu + OFF_H1;     // 32 pair-rows
    float*    xs  = (float*)(smu + OFF_XS);
    uint32_t* wf1 = smu + OFF_WF1;
    uint32_t* wf2 = smu + OFF_WF2;
    uint32_t* wf3 = smu + OFF_WF3;
    float*    b1s = (float*)(smu + OFF_B1);
    float*    b2s = (float*)(smu + OFF_B2);
    float*    b3s = (float*)(smu + OFF_B3);
    float*    ms  = (float*)(smu + OFF_MS);

    const int tid = threadIdx.x;
    const int bx = blockIdx.x, by = blockIdx.y, bb = blockIdx.z;
    const int y0 = by * TH, x0 = bx * TW;

    // ---------------- phase 0: stage weight fragments / biases / mask / halo ----------------
    stage_w<64, 3>(w1, wf1, tid);
    stage_w<32, 4>(w2, wf2, tid);
    stage_w<16, 2>(w3, wf3, tid);

    if (tid < 64)       b1s[tid] = b1[tid];
    else if (tid < 96)  b2s[tid - 64] = b2[tid - 64];
    else if (tid < 112) b3s[tid - 96] = b3[tid - 96];

    if (tid < NPIX) {
        int py = tid >> 4, xx = tid & 15;
        uint32_t w = mask[((size_t)bb * HW + (y0 + py)) * HW + (x0 + xx)];
        ms[tid] = (w != 0u) ? 1.f : 0.f;
    }

    {   // halo 10x18, channel-major fp32, zero-pad outside image
        const float* xb = x + (size_t)bb * HW * HW * CH;
        const int gy0 = y0 - 1, gx0 = x0 - 1;
        for (int i = tid; i < 10 * 18 * 4; i += 256) {
            int q = i & 3, pix = i >> 2;
            int r = pix / 18, cc = pix - r * 18;
            int gr = gy0 + r, gc = gx0 + cc;
            float4 v = make_float4(0.f, 0.f, 0.f, 0.f);
            if ((unsigned)gr < HW && (unsigned)gc < HW)
                v = *(const float4*)&xb[((size_t)gr * HW + gc) * CH + q * 4];
            int base = r * 18 + cc;
            xs[(4 * q + 0) * XCS + base] = v.x;
            xs[(4 * q + 1) * XCS + base] = v.y;
            xs[(4 * q + 2) * XCS + base] = v.z;
            xs[(4 * q + 3) * XCS + base] = v.w;
        }
    }
    __syncthreads();

    // ---------------- phase 1: stencil -> ys (fp16, k-pair packed) ----------------
    {
        const int c = tid >> 4, xx = tid & 15;
        const float* xc = xs + c * XCS;
        __half* ysH = (__half*)ysU;
        float r0a = xc[xx],      r0b = xc[xx + 1],      r0c = xc[xx + 2];
        float r1a = xc[18 + xx], r1b = xc[18 + xx + 1], r1c = xc[18 + xx + 2];
        const int f0 = 3 * c, f1 = 3 * c + 1, f2 = 3 * c + 2;
        __half* pI = ysH + (f0 >> 1) * (2 * YPP) + (f0 & 1);
        __half* pX = ysH + (f1 >> 1) * (2 * YPP) + (f1 & 1);
        __half* pY = ysH + (f2 >> 1) * (2 * YPP) + (f2 & 1);
        #pragma unroll
        for (int py = 0; py < TH; py++) {
            const float* row2 = xc + (py + 2) * 18 + xx;
            float r2a = row2[0], r2b = row2[1], r2c = row2[2];
            float gx = ((r0c - r0a) + 2.f * (r1c - r1a) + (r2c - r2a)) * 0.125f;
            float gy = ((r2a - r0a) + 2.f * (r2b - r0b) + (r2c - r0c)) * 0.125f;
            int p2 = (py * 16 + xx) * 2;
            pI[p2] = __float2half_rn(r1b);
            pX[p2] = __float2half_rn(gx);
            pY[p2] = __float2half_rn(gy);
            r0a = r1a; r0b = r1b; r0c = r1c;
            r1a = r2a; r1b = r2b; r1c = r2c;
        }
    }
    __syncthreads();

    const int lane = tid & 31, warp = tid >> 5;
    const int g = lane >> 2, t = lane & 3;
    const bool geven = (g & 1) == 0;

    // ---------------- phase 2: GEMM1 h1[64][128] = tanh(W1^T @ ys + b1) ----------------
    {
        const int dt = warp & 3, pb = (warp >> 2) * 64;
        const int d0 = dt * 16;
        uint4 A[3];
        #pragma unroll
        for (int kt = 0; kt < 3; kt++)
            A[kt] = *(const uint4*)&wf1[((dt * 3 + kt) * 32 + lane) * 4];
        const float bl = b1s[d0 + g], bh = b1s[d0 + g + 8];
        const int jlo = (d0 + g) >> 1;             // even lanes
        const int jhi = (d0 + g + 7) >> 1;         // odd lanes
        #pragma unroll
        for (int nt = 0; nt < 8; nt++) {
            const int px0 = pb + nt * 8;
            float c0 = bl, c1 = bl, c2 = bh, c3 = bh;
            #pragma unroll
            for (int kt = 0; kt < 3; kt++) {
                uint32_t bv0 = ysU[(8 * kt + t) * YPP + px0 + g];
                uint32_t bv1 = ysU[(8 * kt + t + 4) * YPP + px0 + g];
                mma_f16(c0, c1, c2, c3, A[kt].x, A[kt].y, A[kt].z, A[kt].w, bv0, bv1);
            }
            uint32_t myL = pack2h(tanh_fast(c0), tanh_fast(c1));
            uint32_t myH = pack2h(tanh_fast(c2), tanh_fast(c3));
            uint32_t otL = __shfl_xor_sync(0xffffffffu, myL, 4);
            uint32_t otH = __shfl_xor_sync(0xffffffffu, myH, 4);
            if (geven) {
                h1U[jlo * YPP + px0 + 2 * t]     = lows2(myL, otL);
                h1U[jlo * YPP + px0 + 2 * t + 1] = highs2(myL, otL);
            } else {
                h1U[jhi * YPP + px0 + 2 * t]     = lows2(otH, myH);
                h1U[jhi * YPP + px0 + 2 * t + 1] = highs2(otH, myH);
            }
        }
    }
    __syncthreads();   // ys reads done -> h2 may overwrite aliased region

    // ---------------- phase 3: GEMM2 h2[32][128] = tanh(W2^T @ h1 + b2) ----------------
    {
        const int dt = warp & 1, pb = (warp >> 1) * 32;
        const int d0 = dt * 16;
        uint4 A[4];
        #pragma unroll
        for (int kt = 0; kt < 4; kt++)
            A[kt] = *(const uint4*)&wf2[((dt * 4 + kt) * 32 + lane) * 4];
        const float bl = b2s[d0 + g], bh = b2s[d0 + g + 8];
        const int jlo = (d0 + g) >> 1;
        const int jhi = (d0 + g + 7) >> 1;
        #pragma unroll
        for (int nt = 0; nt < 4; nt++) {
            const int px0 = pb + nt * 8;
            float c0 = bl, c1 = bl, c2 = bh, c3 = bh;
            #pragma unroll
            for (int kt = 0; kt < 4; kt++) {
                uint32_t bv0 = h1U[(8 * kt + t) * YPP + px0 + g];
                uint32_t bv1 = h1U[(8 * kt + t + 4) * YPP + px0 + g];
                mma_f16(c0, c1, c2, c3, A[kt].x, A[kt].y, A[kt].z, A[kt].w, bv0, bv1);
            }
            uint32_t myL = pack2h(tanh_fast(c0), tanh_fast(c1));
            uint32_t myH = pack2h(tanh_fast(c2), tanh_fast(c3));
            uint32_t otL = __shfl_xor_sync(0xffffffffu, myL, 4);
            uint32_t otH = __shfl_xor_sync(0xffffffffu, myH, 4);
            if (geven) {
                h2U[jlo * YPP + px0 + 2 * t]     = lows2(myL, otL);
                h2U[jlo * YPP + px0 + 2 * t + 1] = highs2(myL, otL);
            } else {
                h2U[jhi * YPP + px0 + 2 * t]     = lows2(otH, myH);
                h2U[jhi * YPP + px0 + 2 * t + 1] = highs2(otH, myH);
            }
        }
    }
    __syncthreads();

    // ---------------- phase 4: GEMM3 dx = W3^T @ h2 + b3, fused epilogue ----------------
    {
        uint4 A[2];
        #pragma unroll
        for (int kt = 0; kt < 2; kt++)
            A[kt] = *(const uint4*)&wf3[(kt * 32 + lane) * 4];
        const float bl = b3s[g], bh = b3s[g + 8];
        float* ob = out + (((size_t)bb * HW + y0) * HW + x0) * CH;
        #pragma unroll
        for (int nt = 0; nt < 2; nt++) {
            const int px0 = warp * 16 + nt * 8;
            float c0 = bl, c1 = bl, c2 = bh, c3 = bh;
            #pragma unroll
            for (int kt = 0; kt < 2; kt++) {
                uint32_t bv0 = h2U[(8 * kt + t) * YPP + px0 + g];
                uint32_t bv1 = h2U[(8 * kt + t + 4) * YPP + px0 + g];
                mma_f16(c0, c1, c2, c3, A[kt].x, A[kt].y, A[kt].z, A[kt].w, bv0, bv1);
            }
            const int p0 = px0 + 2 * t, p1 = p0 + 1;
            const float m0 = ms[p0], m1 = ms[p1];
            const int py0 = p0 >> 4, xx0 = p0 & 15;
            const int py1 = p1 >> 4, xx1 = p1 & 15;
            const int hb0 = (py0 + 1) * 18 + (xx0 + 1);
            const int hb1 = (py1 + 1) * 18 + (xx1 + 1);
            float* o0 = ob + ((size_t)py0 * HW + xx0) * CH;
            float* o1 = ob + ((size_t)py1 * HW + xx1) * CH;
            o0[g]     = xs[g * XCS + hb0]       + c0 * m0;
            o1[g]     = xs[g * XCS + hb1]       + c1 * m1;
            o0[g + 8] = xs[(g + 8) * XCS + hb0] + c2 * m0;
            o1[g + 8] = xs[(g + 8) * XCS + hb1] + c3 * m1;
        }
    }
}

extern "C" void kernel_launch(void* const* d_in, const int* in_sizes, int n_in,
                              void* d_out, int out_size)
{
    const float* x  = (const float*)d_in[0];
    const float* w1 = (const float*)d_in[1];
    const float* b1 = (const float*)d_in[2];
    const float* w2 = (const float*)d_in[3];
    const float* b2 = (const float*)d_in[4];
    const float* w3 = (const float*)d_in[5];
    const float* b3 = (const float*)d_in[6];
    const uint32_t* mask = (const uint32_t*)d_in[7];
    float* out = (float*)d_out;

    cudaFuncSetAttribute(nca_step_kernel,
                         cudaFuncAttributeMaxDynamicSharedMemorySize, SMEM_BYTES);
    dim3 grid(HW / TW, HW / TH, 16);
    nca_step_kernel<<<grid, 256, SMEM_BYTES>>>(x, w1, b1, w2, b2, w3, b3, mask, out);
}